// round 16
// baseline (speedup 1.0000x reference)
#include <cuda_runtime.h>

// Problem constants (shapes fixed by the dataset)
#define BATCH 64
#define FT    51200            // 80 * 640 elements per (channel,batch) slab
#define BFT   3276800          // 64*80*640 per-channel flattened length
#define NAUX  32
#define WPB   1600             // FT/32 bitset words per batch
#define NPAIR 2048             // NAUX * BATCH
#define NFIFTH 5               // aux slab split
#define F4_PER_FIFTH 2560      // 12800/5
#define AUX_F4_PER_WARP 320    // 2560/8 warps
#define AUX_NBLK (NPAIR * NFIFTH)   // 10240
#define STR_NBLK 1600          // 12800 warps x 256 elems = 3276800
#define FULLM 0xffffffffu

// Largest float strictly below 20.0f: (x > TH_LT) <=> (x >= 20.0f)
#define TH_LT __int_as_float(0x419FFFFF)

// Scratch (__device__ globals — no allocations). Partials TRANSPOSED
// [fifth][pair] so fin's loads coalesce (strided grid-2 fin measured at
// 5.1-5.3us twice). Fully overwritten every launch -> replay-deterministic.
__device__ unsigned g_sbits[BATCH * WPB];
__device__ int g_pi[NFIFTH * NPAIR];   // partial intersections
__device__ int g_pc[NFIFTH * NPAIR];   // partial aux peak counts
__device__ int g_pa[NFIFTH * NPAIR];   // partial 8*c1 accumulators

__device__ __forceinline__ float finf() { return __int_as_float(0x7f800000); }

__device__ __forceinline__ unsigned nib4(float4 v, float l, float r) {
    unsigned b0 = (v.x > fmaxf(fmaxf(l,   v.y), TH_LT)) ? 1u : 0u;
    unsigned b1 = (v.y > fmaxf(fmaxf(v.x, v.z), TH_LT)) ? 2u : 0u;
    unsigned b2 = (v.z > fmaxf(fmaxf(v.y, v.w), TH_LT)) ? 4u : 0u;
    unsigned b3 = (v.w > fmaxf(fmaxf(v.z, r),   TH_LT)) ? 8u : 0u;
    return (b0 | b1) | (b2 | b3);
}

// ---------------------------------------------------------------------------
// Strain kernel: R9 loop-free form (regs=20 — the leanest measured). Five
// structurally distinct variants all measured 6.1-7.3us -> this kernel sits
// at its launch/ramp floor; form no longer matters. 1600 blocks x 256 thr.
// ---------------------------------------------------------------------------
__global__ __launch_bounds__(256, 8) void strain_kernel(const float* __restrict__ s) {
    const int tid = threadIdx.x, lane = tid & 31, w = tid >> 5;
    const int warp_id = blockIdx.x * 8 + w;          // 0..12799
    const int q0 = warp_id * 64;                     // first float4 of warp
    const int gelem = q0 * 4;                        // 256 elements per warp
    const float4* p4 = reinterpret_cast<const float4*>(s) + q0;

    const float4 v0 = p4[2 * lane];
    const float4 v1 = p4[2 * lane + 1];

    float l = __shfl_up_sync(FULLM, v1.w, 1);
    if (lane == 0)  l = (gelem == 0) ? finf() : __ldg(s + gelem - 1);
    float r = __shfl_down_sync(FULLM, v0.x, 1);
    if (lane == 31) r = (gelem + 256 == BFT) ? finf() : __ldg(s + gelem + 256);

    const unsigned byte = nib4(v0, l, v1.x) | (nib4(v1, v0.w, r) << 4);
    unsigned word = byte << ((lane & 3) << 3);
    word |= __shfl_xor_sync(FULLM, word, 1);
    word |= __shfl_xor_sync(FULLM, word, 2);
    if ((lane & 3) == 0) g_sbits[(gelem >> 5) + (lane >> 2)] = word;
}

// ---------------------------------------------------------------------------
// Aux kernel: inner loop byte-identical to the proven R9 form (~58us, ~88% of
// DRAM spec in fast sessions). 10240 blocks (2048 pairs x 5 fifths), 256
// threads, occ cap 4 (LOAD-BEARING: R6 measured occ-8 at DRAM 68.7% —
// cross-CTA L1tex-queue contention), __ldcs streaming, plain partial stores
// (transposed index), no atomics/fences (fused variants measured +6-9us).
// ---------------------------------------------------------------------------
__global__ __launch_bounds__(256, 4) void aux_kernel(const float* __restrict__ aux) {
    const int blk = blockIdx.x;
    const int pair = blk / NFIFTH, fifth = blk - pair * NFIFTH;
    const int b = pair & 63, n = pair >> 6;
    const int tid = threadIdx.x, lane = tid & 31, w = tid >> 5;

    const float* ch = aux + (size_t)n * BFT;
    const int slab4 = fifth * F4_PER_FIFTH + w * AUX_F4_PER_WARP;
    const int gelem = b * FT + slab4 * 4;
    const float4* p4 = reinterpret_cast<const float4*>(ch + gelem);
    const unsigned* __restrict__ swp = g_sbits + b * WPB + (slab4 >> 3) + (lane >> 3);
    const int sh = (lane & 7) << 2;

    float carry = (gelem == 0) ? finf() : __ldg(ch + gelem - 1);
    const float rlast = (gelem + 4 * AUX_F4_PER_WARP == BFT)
                            ? finf()
                            : __ldg(ch + gelem + 4 * AUX_F4_PER_WARP);
    int inter = 0, c2 = 0, c1a = 0;
    float4 v = __ldcs(&p4[lane]);
#pragma unroll
    for (int it = 0; it < 10; ++it) {
        float4 vn = v;
        if (it < 9) vn = __ldcs(&p4[(it + 1) * 32 + lane]);
        float l = __shfl_up_sync(FULLM, v.w, 1);
        if (lane == 0) l = carry;
        float r = __shfl_down_sync(FULLM, v.x, 1);
        float r31 = (it < 9) ? __shfl_sync(FULLM, vn.x, 0) : rlast;
        if (lane == 31) r = r31;
        carry = __shfl_sync(FULLM, v.w, 31);

        unsigned nib = nib4(v, l, r);
        unsigned sw = __ldg(swp + it * 4);            // 8 lanes broadcast same word
        inter += __popc((sw >> sh) & nib);
        c2 += __popc(nib);
        c1a += __popc(sw);                            // sums to 8*c1 over the slab
        v = vn;
    }

    // Block reduce 3 ints (8 warps).
    __shared__ int sm0[8], sm1[8], sm2[8];
#pragma unroll
    for (int o = 16; o > 0; o >>= 1) {
        inter += __shfl_down_sync(FULLM, inter, o);
        c2    += __shfl_down_sync(FULLM, c2, o);
        c1a   += __shfl_down_sync(FULLM, c1a, o);
    }
    if (lane == 0) { sm0[w] = inter; sm1[w] = c2; sm2[w] = c1a; }
    __syncthreads();
    if (tid == 0) {
        int a = 0, bb = 0, c = 0;
#pragma unroll
        for (int k = 0; k < 8; ++k) { a += sm0[k]; bb += sm1[k]; c += sm2[k]; }
        const int pidx = fifth * NPAIR + pair;        // transposed for coalesced fin
        g_pi[pidx] = a; g_pc[pidx] = bb; g_pa[pidx] = c;
    }
}

// ---------------------------------------------------------------------------
// Finalize: 8 blocks x 256 threads, one thread per pair; all 15 loads fully
// coalesced (stride-1 in pair index thanks to the transposed layout).
// ---------------------------------------------------------------------------
__global__ __launch_bounds__(256) void fin_kernel(float* __restrict__ out, int half) {
    const int idx = blockIdx.x * 256 + threadIdx.x;   // pair id, 0..2047
    int ti = 0, tc = 0, ta = 0;
#pragma unroll
    for (int k = 0; k < NFIFTH; ++k) {
        ti += g_pi[k * NPAIR + idx];
        tc += g_pc[k * NPAIR + idx];
        ta += g_pa[k * NPAIR + idx];
    }
    const int c1 = ta >> 3;
    const int uni = c1 + tc - ti;
    float jac, ratio;
    if (uni == 0) {
        jac = 1.0f; ratio = 1.0f;                     // empty-vs-empty
    } else {
        jac = (float)ti / (float)uni;
        ratio = (c1 == 0) ? 0.0f : (float)ti / (float)c1;  // nan_to_num(0/0)->0
    }
    out[idx] = jac;
    out[half + idx] = ratio;
}

extern "C" void kernel_launch(void* const* d_in, const int* in_sizes, int n_in,
                              void* d_out, int out_size) {
    const float* strain = (const float*)d_in[0];
    const float* aux    = (const float*)d_in[1];
    if (n_in >= 2 && in_sizes[0] != BFT) {            // defensive order check
        strain = (const float*)d_in[1];
        aux    = (const float*)d_in[0];
    }
    float* out = (float*)d_out;

    strain_kernel<<<STR_NBLK, 256>>>(strain);
    aux_kernel<<<AUX_NBLK, 256>>>(aux);
    fin_kernel<<<NPAIR / 256, 256>>>(out, out_size >> 1);
}

// round 17
// speedup vs baseline: 1.1471x; 1.1471x over previous
#include <cuda_runtime.h>

// Problem constants (shapes fixed by the dataset)
#define BATCH 64
#define FT    51200            // 80 * 640 elements per (channel,batch) slab
#define BFT   3276800          // 64*80*640 per-channel flattened length
#define NAUX  32
#define WPB   1600             // FT/32 bitset words per batch
#define NPAIR 2048             // NAUX * BATCH
#define NFIFTH 5               // aux slab split
#define F4_PER_FIFTH 2560      // 12800/5
#define AUX_F4_PER_WARP 320    // 2560/8 warps
#define AUX_NBLK (NPAIR * NFIFTH)   // 10240
#define STR_NBLK 1600          // 12800 warps x 256 elems = 3276800
#define FULLM 0xffffffffu

// Largest float strictly below 20.0f: (x > TH_LT) <=> (x >= 20.0f)
#define TH_LT __int_as_float(0x419FFFFF)

// Scratch (__device__ globals — no allocations). ORIGINAL [pair*5+fifth]
// layout: every transposed build (R13/R15/R16) measured 74-76us vs 66-68us
// for every original-layout build — reverted on that correlation. Fully
// overwritten every launch -> deterministic across graph replays.
__device__ unsigned g_sbits[BATCH * WPB];
__device__ int g_pi[AUX_NBLK];   // partial intersections
__device__ int g_pc[AUX_NBLK];   // partial aux peak counts
__device__ int g_pa[AUX_NBLK];   // partial 8*c1 accumulators

__device__ __forceinline__ float finf() { return __int_as_float(0x7f800000); }

__device__ __forceinline__ unsigned nib4(float4 v, float l, float r) {
    unsigned b0 = (v.x > fmaxf(fmaxf(l,   v.y), TH_LT)) ? 1u : 0u;
    unsigned b1 = (v.y > fmaxf(fmaxf(v.x, v.z), TH_LT)) ? 2u : 0u;
    unsigned b2 = (v.z > fmaxf(fmaxf(v.y, v.w), TH_LT)) ? 4u : 0u;
    unsigned b3 = (v.w > fmaxf(fmaxf(v.z, r),   TH_LT)) ? 8u : 0u;
    return (b0 | b1) | (b2 | b3);
}

// ---------------------------------------------------------------------------
// Strain kernel: R9 loop-free form, byte-exact (regs=20). Five structurally
// distinct variants all measured 6.1-7.3us -> at its launch/ramp floor.
// 1600 blocks x 256 threads.
// ---------------------------------------------------------------------------
__global__ __launch_bounds__(256, 8) void strain_kernel(const float* __restrict__ s) {
    const int tid = threadIdx.x, lane = tid & 31, w = tid >> 5;
    const int warp_id = blockIdx.x * 8 + w;          // 0..12799
    const int q0 = warp_id * 64;                     // first float4 of warp
    const int gelem = q0 * 4;                        // 256 elements per warp
    const float4* p4 = reinterpret_cast<const float4*>(s) + q0;

    const float4 v0 = p4[2 * lane];
    const float4 v1 = p4[2 * lane + 1];

    float l = __shfl_up_sync(FULLM, v1.w, 1);
    if (lane == 0)  l = (gelem == 0) ? finf() : __ldg(s + gelem - 1);
    float r = __shfl_down_sync(FULLM, v0.x, 1);
    if (lane == 31) r = (gelem + 256 == BFT) ? finf() : __ldg(s + gelem + 256);

    const unsigned byte = nib4(v0, l, v1.x) | (nib4(v1, v0.w, r) << 4);
    unsigned word = byte << ((lane & 3) << 3);
    word |= __shfl_xor_sync(FULLM, word, 1);
    word |= __shfl_xor_sync(FULLM, word, 2);
    if ((lane & 3) == 0) g_sbits[(gelem >> 5) + (lane >> 2)] = word;
}

// ---------------------------------------------------------------------------
// Aux kernel: byte-exact R9 (proven 66.3/67.6 twice; ~58us standalone, ~90%
// of HBM). 10240 blocks (2048 pairs x 5 fifths), 256 threads, occ cap 4
// (LOAD-BEARING: occ-8 measured DRAM 68.7% — cross-CTA L1tex contention),
// __ldcs streaming, plain partial stores in ORIGINAL layout, no
// atomics/fences (fused variants measured +6-9us).
// ---------------------------------------------------------------------------
__global__ __launch_bounds__(256, 4) void aux_kernel(const float* __restrict__ aux) {
    const int blk = blockIdx.x;
    const int pair = blk / NFIFTH, fifth = blk - pair * NFIFTH;
    const int b = pair & 63, n = pair >> 6;
    const int tid = threadIdx.x, lane = tid & 31, w = tid >> 5;

    const float* ch = aux + (size_t)n * BFT;
    const int slab4 = fifth * F4_PER_FIFTH + w * AUX_F4_PER_WARP;
    const int gelem = b * FT + slab4 * 4;
    const float4* p4 = reinterpret_cast<const float4*>(ch + gelem);
    const unsigned* __restrict__ swp = g_sbits + b * WPB + (slab4 >> 3) + (lane >> 3);
    const int sh = (lane & 7) << 2;

    float carry = (gelem == 0) ? finf() : __ldg(ch + gelem - 1);
    const float rlast = (gelem + 4 * AUX_F4_PER_WARP == BFT)
                            ? finf()
                            : __ldg(ch + gelem + 4 * AUX_F4_PER_WARP);
    int inter = 0, c2 = 0, c1a = 0;
    float4 v = __ldcs(&p4[lane]);
#pragma unroll
    for (int it = 0; it < 10; ++it) {
        float4 vn = v;
        if (it < 9) vn = __ldcs(&p4[(it + 1) * 32 + lane]);
        float l = __shfl_up_sync(FULLM, v.w, 1);
        if (lane == 0) l = carry;
        float r = __shfl_down_sync(FULLM, v.x, 1);
        float r31 = (it < 9) ? __shfl_sync(FULLM, vn.x, 0) : rlast;
        if (lane == 31) r = r31;
        carry = __shfl_sync(FULLM, v.w, 31);

        unsigned nib = nib4(v, l, r);
        unsigned sw = __ldg(swp + it * 4);            // 8 lanes broadcast same word
        inter += __popc((sw >> sh) & nib);
        c2 += __popc(nib);
        c1a += __popc(sw);                            // sums to 8*c1 over the slab
        v = vn;
    }

    // Block reduce 3 ints (8 warps).
    __shared__ int sm0[8], sm1[8], sm2[8];
#pragma unroll
    for (int o = 16; o > 0; o >>= 1) {
        inter += __shfl_down_sync(FULLM, inter, o);
        c2    += __shfl_down_sync(FULLM, c2, o);
        c1a   += __shfl_down_sync(FULLM, c1a, o);
    }
    if (lane == 0) { sm0[w] = inter; sm1[w] = c2; sm2[w] = c1a; }
    __syncthreads();
    if (tid == 0) {
        int a = 0, bb = 0, c = 0;
#pragma unroll
        for (int k = 0; k < 8; ++k) { a += sm0[k]; bb += sm1[k]; c += sm2[k]; }
        g_pi[blk] = a; g_pc[blk] = bb; g_pa[blk] = c;
    }
}

// ---------------------------------------------------------------------------
// Finalize: 8 blocks x 256 threads (one pair per thread), ORIGINAL strided
// addressing — 15 independent loads per thread (MLP=15, all L2 hits), spread
// across 8 SMs instead of 2. Aux is untouched by this change.
// ---------------------------------------------------------------------------
__global__ __launch_bounds__(256) void fin_kernel(float* __restrict__ out, int half) {
    const int idx = blockIdx.x * 256 + threadIdx.x;   // pair id, 0..2047
    int ti = 0, tc = 0, ta = 0;
#pragma unroll
    for (int k = 0; k < NFIFTH; ++k) {
        ti += g_pi[idx * NFIFTH + k];
        tc += g_pc[idx * NFIFTH + k];
        ta += g_pa[idx * NFIFTH + k];
    }
    const int c1 = ta >> 3;
    const int uni = c1 + tc - ti;
    float jac, ratio;
    if (uni == 0) {
        jac = 1.0f; ratio = 1.0f;                     // empty-vs-empty
    } else {
        jac = (float)ti / (float)uni;
        ratio = (c1 == 0) ? 0.0f : (float)ti / (float)c1;  // nan_to_num(0/0)->0
    }
    out[idx] = jac;
    out[half + idx] = ratio;
}

extern "C" void kernel_launch(void* const* d_in, const int* in_sizes, int n_in,
                              void* d_out, int out_size) {
    const float* strain = (const float*)d_in[0];
    const float* aux    = (const float*)d_in[1];
    if (n_in >= 2 && in_sizes[0] != BFT) {            // defensive order check
        strain = (const float*)d_in[1];
        aux    = (const float*)d_in[0];
    }
    float* out = (float*)d_out;

    strain_kernel<<<STR_NBLK, 256>>>(strain);
    aux_kernel<<<AUX_NBLK, 256>>>(aux);
    fin_kernel<<<NPAIR / 256, 256>>>(out, out_size >> 1);
}